// round 10
// baseline (speedup 1.0000x reference)
#include <cuda_runtime.h>
#include <math.h>
#include <stdint.h>

#define NND 50000
#define NE  600000
#define AD  75
#define HH  128
#define NL  4
#define NG  128
#define NB1 196   // ceil(NND/256)

#define GSMEM_BYTES (96*1024)   // 64KB A-frag + 32KB B-frag
#define NWTILES (2 + NL*8 + NL*6)   // 58 weight 64-col tiles

// ---------------- scratch (static device globals; no runtime alloc) ----------------
__device__ float g_x  [NND*HH];
__device__ float g_h  [NND*HH];
__device__ float g_m  [NND*HH];
__device__ float g_agg[NND*HH];
__device__ float g_gi [NND*3*HH];
__device__ float g_gh [NND*3*HH];
__device__ float g_as [NND];
__device__ float g_ad [NND];
__device__ float g_stats[2*HH];
__device__ float g_gr [NG*HH];
__device__ float g_Wpad[HH*HH];
__device__ float g_Wmh [NL*512*HH];
__device__ float g_bmh [NL*512];
__device__ float g_Wf  [NWTILES*8192];
__device__ int   g_deg [NND];
__device__ int   g_off [NND+1];
__device__ int   g_cur [NND];
__device__ int   g_blk [256];
__device__ int   g_esrc[NE];
__device__ int   g_edst[NE];
__device__ float g_eatt[NE];

__device__ __forceinline__ float sigm(float v) { return 1.f / (1.f + expf(-v)); }

__device__ __forceinline__ unsigned f2tf(float x) {
    unsigned u;
    asm("cvt.rna.tf32.f32 %0, %1;" : "=r"(u) : "f"(x));
    return u;
}

// ---------------- setup: pads + weight packing ----------------
__global__ void k_prep(const float* __restrict__ nf, const float* __restrict__ embW,
                       const float* __restrict__ msgW, const float* __restrict__ msgb,
                       const float* __restrict__ Whh, const float* __restrict__ bhh,
                       float* __restrict__ nfp, float* __restrict__ Wpad,
                       float* __restrict__ Wmh, float* __restrict__ bmh)
{
    int i = blockIdx.x * blockDim.x + threadIdx.x;
    if (i < NND * HH) {
        int n = i >> 7, c = i & 127;
        nfp[i] = (c < AD) ? nf[n * AD + c] : 0.f;
    }
    if (i < HH * HH) {
        int r = i >> 7, c = i & 127;
        Wpad[i] = (c < AD) ? embW[r * AD + c] : 0.f;
    }
    if (i < NL * 512 * HH) {
        int l = i / (512 * HH);
        int rem = i - l * 512 * HH;
        int r = rem >> 7, c = rem & 127;
        Wmh[i] = (r < HH) ? msgW[(size_t)l * HH * HH + r * HH + c]
                          : Whh[(size_t)l * 3 * HH * HH + (size_t)(r - HH) * HH + c];
    }
    if (i < NL * 512) {
        int l = i >> 9, r = i & 511;
        bmh[i] = (r < HH) ? msgb[l * HH + r] : bhh[l * 3 * HH + (r - HH)];
    }
}

// ---------------- weight fragmentization: B-fragment layout per 64-col tile ----------------
// Tile layout (8192 floats): [nt 0..7][kc 0..15][lane 0..31][b0,b1]
// b0 = W[n0 + nt*8 + (lane>>2)][kc*8 + (lane&3)], b1 = same row, col+4. tf32-rounded.
__global__ void k_wfrag(const float* __restrict__ Wpad, const float* __restrict__ Wmh,
                        const float* __restrict__ Wih, float* __restrict__ Wf)
{
    int b = blockIdx.x;             // tile id 0..57
    const float* src; int rbase;
    if (b < 2)       { src = Wpad; rbase = b * 64; }
    else if (b < 34) { int q = b - 2;  src = Wmh + (size_t)(q >> 3) * 512 * HH; rbase = (q & 7) * 64; }
    else             { int q = b - 34; src = Wih + (size_t)(q / 6) * 3 * HH * HH; rbase = (q % 6) * 64; }
    float* dst = Wf + (size_t)b * 8192;
    int lane = threadIdx.x & 31;
    int r = lane >> 2, c = lane & 3;
    for (int i = 0; i < 16; i++) {
        int slot = threadIdx.x + i * 256;     // 0..4095
        int kcnt = slot >> 5;
        int kc = kcnt & 15, nt = kcnt >> 4;
        int row = rbase + nt * 8 + r;
        int col = kc * 8 + c;
        float2 o;
        o.x = __uint_as_float(f2tf(src[(size_t)row * 128 + col]));
        o.y = __uint_as_float(f2tf(src[(size_t)row * 128 + col + 4]));
        *(float2*)(dst + slot * 2) = o;
    }
}

__global__ void k_zinit(int* __restrict__ deg, float* __restrict__ gr)
{
    int i = blockIdx.x * blockDim.x + threadIdx.x;
    if (i < NND) deg[i] = 0;
    if (i < NG * HH) gr[i] = 0.f;
}

// ---------------- CSR build ----------------
__global__ void k_hist(const int* __restrict__ ei, int* __restrict__ deg)
{
    int e = blockIdx.x * blockDim.x + threadIdx.x;
    if (e < NE) atomicAdd(deg + __ldg(ei + NE + e), 1);
}

__global__ void k_scan1(const int* __restrict__ deg, int* __restrict__ off,
                        int* __restrict__ blk)
{
    __shared__ int s[256];
    int tx = threadIdx.x;
    int i = blockIdx.x * 256 + tx;
    int v = (i < NND) ? deg[i] : 0;
    s[tx] = v;
    __syncthreads();
    for (int o = 1; o < 256; o <<= 1) {
        int t = 0;
        if (tx >= o) t = s[tx - o];
        __syncthreads();
        if (tx >= o) s[tx] += t;
        __syncthreads();
    }
    if (i < NND) off[i] = s[tx] - v;
    if (tx == 255) blk[blockIdx.x] = s[255];
}

__global__ void k_scan2(int* __restrict__ blk)
{
    __shared__ int s[256];
    int tx = threadIdx.x;
    int v = (tx < NB1) ? blk[tx] : 0;
    s[tx] = v;
    __syncthreads();
    for (int o = 1; o < 256; o <<= 1) {
        int t = 0;
        if (tx >= o) t = s[tx - o];
        __syncthreads();
        if (tx >= o) s[tx] += t;
        __syncthreads();
    }
    blk[tx] = s[tx] - v;
}

__global__ void k_scan3(int* __restrict__ off, const int* __restrict__ blk,
                        int* __restrict__ cur)
{
    int i = blockIdx.x * 256 + threadIdx.x;
    if (i < NND) {
        int o = off[i] + blk[i >> 8];
        off[i] = o;
        cur[i] = o;
    }
    if (i == 0) off[NND] = NE;
}

__global__ void k_fill(const int* __restrict__ ei, int* __restrict__ cur,
                       int* __restrict__ esrc, int* __restrict__ edst)
{
    int e = blockIdx.x * blockDim.x + threadIdx.x;
    if (e >= NE) return;
    int s = __ldg(ei + e);
    int d = __ldg(ei + NE + e);
    int pos = atomicAdd(cur + d, 1);
    esrc[pos] = s;
    edst[pos] = d;
}

// ---------------- per-edge attention (CSR order) ----------------
__global__ void k_att(const int* __restrict__ esrc, const int* __restrict__ edst,
                      const float* __restrict__ as_, const float* __restrict__ ad_,
                      const float* __restrict__ attb, float* __restrict__ eatt)
{
    int p = blockIdx.x * blockDim.x + threadIdx.x;
    if (p >= NE) return;
    float a = __ldg(as_ + __ldg(esrc + p)) + __ldg(ad_ + __ldg(edst + p)) + __ldg(attb);
    eatt[p] = 1.f / (1.f + expf(-a));
}

// ---------------- gather aggregation ----------------
__global__ __launch_bounds__(256) void k_gather(
    const int* __restrict__ off, const int* __restrict__ esrc,
    const float* __restrict__ eatt, const float* __restrict__ m,
    float* __restrict__ agg)
{
    int n = (blockIdx.x * blockDim.x + threadIdx.x) >> 5;
    int lane = threadIdx.x & 31;
    if (n >= NND) return;
    int p = __ldg(off + n);
    int e = __ldg(off + n + 1);
    float4 acc = make_float4(0.f, 0.f, 0.f, 0.f);
    for (; p + 1 < e; p += 2) {
        int s0 = __ldg(esrc + p);
        int s1 = __ldg(esrc + p + 1);
        float a0 = __ldg(eatt + p);
        float a1 = __ldg(eatt + p + 1);
        float4 v0 = *(const float4*)(m + (size_t)s0 * HH + lane * 4);
        float4 v1 = *(const float4*)(m + (size_t)s1 * HH + lane * 4);
        acc.x += v0.x * a0 + v1.x * a1;
        acc.y += v0.y * a0 + v1.y * a1;
        acc.z += v0.z * a0 + v1.z * a1;
        acc.w += v0.w * a0 + v1.w * a1;
    }
    if (p < e) {
        int s0 = __ldg(esrc + p);
        float a0 = __ldg(eatt + p);
        float4 v0 = *(const float4*)(m + (size_t)s0 * HH + lane * 4);
        acc.x += v0.x * a0; acc.y += v0.y * a0;
        acc.z += v0.z * a0; acc.w += v0.w * a0;
    }
    *(float4*)(agg + (size_t)n * HH + lane * 4) = acc;
}

// ---------------- tf32 mma.sync GEMM, fragment-layout smem ----------------
// C[M, 64*gridDim.y] = A[M,128] @ W^T + bias. Block tile 128x64, 8 warps (4m x 2n),
// warp tile 32x32 (2 mtiles x 4 ntiles of m16n8k8). A gathered global->fragment
// layout once (full K), B copied linearly from precomputed fragment table.
// Output cols < split -> C1 (row stride s1), >= split -> C2 at col-split (stride s2).
template <bool RELU>
__global__ __launch_bounds__(256, 1) void k_gemm_tc(
    const float* __restrict__ A, const float* __restrict__ Wf,
    const float* __restrict__ bias, float* __restrict__ C1, float* __restrict__ C2,
    int M, int split, int s1, int s2, float* zbuf)
{
    extern __shared__ float fs[];
    float* AF = fs;            // [mt 0..7][kc 0..15][lane][a0..a3] = 16384 floats
    float* BF = fs + 16384;    // [nt 0..7][kc 0..15][lane][b0,b1]  = 8192 floats
    const int tid = threadIdx.x;
    if (zbuf != nullptr && blockIdx.x == 0 && blockIdx.y == 0 && tid < 256)
        zbuf[tid] = 0.f;
    const int m0 = blockIdx.x * 128;
    const int n0 = blockIdx.y * 64;
    const int lane = tid & 31;
    const int wid = tid >> 5;
    const int lr = lane >> 2;
    const int lc = lane & 3;

    // stage B: linear copy of precomputed fragment tile
    {
        const float4* src = (const float4*)(Wf + (size_t)blockIdx.y * 8192);
        float4* dst = (float4*)BF;
        #pragma unroll
        for (int i = 0; i < 8; i++)
            dst[tid + i * 256] = src[tid + i * 256];
    }
    // stage A: gather into fragment layout (tf32-rounded)
    #pragma unroll
    for (int i = 0; i < 16; i++) {
        int slot = tid + i * 256;          // (kcmt, lane)
        int kcmt = slot >> 5;
        int kc = kcmt & 15, mt = kcmt >> 4;
        int row = m0 + mt * 16 + lr;
        int col = kc * 8 + lc;
        float4 v = make_float4(0.f, 0.f, 0.f, 0.f);
        if (row < M) {
            v.x = __ldg(A + (size_t)row * 128 + col);
            v.z = __ldg(A + (size_t)row * 128 + col + 4);
        }
        if (row + 8 < M) {
            v.y = __ldg(A + (size_t)(row + 8) * 128 + col);
            v.w = __ldg(A + (size_t)(row + 8) * 128 + col + 4);
        }
        float4 o;
        o.x = __uint_as_float(f2tf(v.x));
        o.y = __uint_as_float(f2tf(v.y));
        o.z = __uint_as_float(f2tf(v.z));
        o.w = __uint_as_float(f2tf(v.w));
        *(float4*)(AF + (size_t)slot * 4) = o;
    }
    __syncthreads();

    const int wm = (wid & 3) * 2;    // first of 2 mtiles
    const int wn = (wid >> 2) * 4;   // first of 4 ntiles
    float acc[2][4][4];
    #pragma unroll
    for (int i = 0; i < 2; i++)
        #pragma unroll
        for (int j = 0; j < 4; j++)
            #pragma unroll
            for (int q = 0; q < 4; q++) acc[i][j][q] = 0.f;

    #pragma unroll
    for (int kc = 0; kc < 16; kc++) {
        float4 af[2];
        af[0] = *(const float4*)(AF + (((wm + 0) * 16 + kc) * 32 + lane) * 4);
        af[1] = *(const float4*)(AF + (((wm + 1) * 16 + kc) * 32 + lane) * 4);
        float2 bf[4];
        #pragma unroll
        for (int nt = 0; nt < 4; nt++)
            bf[nt] = *(const float2*)(BF + (((wn + nt) * 16 + kc) * 32 + lane) * 2);
        #pragma unroll
        for (int mt = 0; mt < 2; mt++)
            #pragma unroll
            for (int nt = 0; nt < 4; nt++) {
                asm volatile(
                    "mma.sync.aligned.m16n8k8.row.col.f32.tf32.tf32.f32 "
                    "{%0,%1,%2,%3}, {%4,%5,%6,%7}, {%8,%9}, {%0,%1,%2,%3};\n"
                    : "+f"(acc[mt][nt][0]), "+f"(acc[mt][nt][1]),
                      "+f"(acc[mt][nt][2]), "+f"(acc[mt][nt][3])
                    : "r"(__float_as_uint(af[mt].x)), "r"(__float_as_uint(af[mt].y)),
                      "r"(__float_as_uint(af[mt].z)), "r"(__float_as_uint(af[mt].w)),
                      "r"(__float_as_uint(bf[nt].x)), "r"(__float_as_uint(bf[nt].y)));
            }
    }

    // epilogue
    float* Cp; int cstr, coff;
    if (n0 < split) { Cp = C1; cstr = s1; coff = 0; }
    else            { Cp = C2; cstr = s2; coff = split; }
    #pragma unroll
    for (int mt = 0; mt < 2; mt++) {
        #pragma unroll
        for (int nt = 0; nt < 4; nt++) {
            int cb = n0 + (wn + nt) * 8 + lc * 2;
            float2 bv = *(const float2*)(bias + cb);
            int cc = cb - coff;
            int r0 = m0 + (wm + mt) * 16 + lr;
            if (r0 < M) {
                float2 o;
                o.x = acc[mt][nt][0] + bv.x;
                o.y = acc[mt][nt][1] + bv.y;
                if (RELU) { o.x = fmaxf(o.x, 0.f); o.y = fmaxf(o.y, 0.f); }
                *(float2*)(Cp + (size_t)r0 * cstr + cc) = o;
            }
            int r1 = r0 + 8;
            if (r1 < M) {
                float2 o;
                o.x = acc[mt][nt][2] + bv.x;
                o.y = acc[mt][nt][3] + bv.y;
                if (RELU) { o.x = fmaxf(o.x, 0.f); o.y = fmaxf(o.y, 0.f); }
                *(float2*)(Cp + (size_t)r1 * cstr + cc) = o;
            }
        }
    }
}

// ---------------- fused GRU elementwise + BN stats ----------------
__global__ __launch_bounds__(256) void k_gru_bn(
    const float* __restrict__ gi, const float* __restrict__ gh,
    const float* __restrict__ x, float* __restrict__ h, float* __restrict__ stats)
{
    __shared__ float ss[256];
    __shared__ float sq[256];
    int c  = threadIdx.x & 127;
    int ry = threadIdx.x >> 7;
    float s = 0.f, q = 0.f;
    for (int r = blockIdx.x * 2 + ry; r < NND; r += gridDim.x * 2) {
        const float* gin = gi + (size_t)r * 384;
        const float* ghn = gh + (size_t)r * 384;
        float rr = sigm(gin[c]       + ghn[c]);
        float zz = sigm(gin[c + 128] + ghn[c + 128]);
        float nn = tanhf(gin[c + 256] + rr * ghn[c + 256]);
        float v  = (1.f - zz) * nn + zz * x[(size_t)r * 128 + c];
        h[(size_t)r * 128 + c] = v;
        s += v; q += v * v;
    }
    ss[threadIdx.x] = s;
    sq[threadIdx.x] = q;
    __syncthreads();
    if (threadIdx.x < 128) {
        atomicAdd(stats + c, ss[threadIdx.x] + ss[threadIdx.x + 128]);
        atomicAdd(stats + 128 + c, sq[threadIdx.x] + sq[threadIdx.x + 128]);
    }
}

// ---------------- BN stats (embedding stage) ----------------
__global__ void k_bnstats(const float* __restrict__ h, float* __restrict__ stats)
{
    __shared__ float ss[8][128];
    __shared__ float sq[8][128];
    int c = threadIdx.x;
    float s = 0.f, q = 0.f;
    for (int r = blockIdx.x * 8 + threadIdx.y; r < NND; r += gridDim.x * 8) {
        float v = h[(size_t)r * 128 + c];
        s += v; q += v * v;
    }
    ss[threadIdx.y][c] = s;
    sq[threadIdx.y][c] = q;
    __syncthreads();
    if (threadIdx.y == 0) {
        #pragma unroll
        for (int y = 1; y < 8; y++) { s += ss[y][c]; q += sq[y][c]; }
        atomicAdd(stats + c, s);
        atomicAdd(stats + 128 + c, q);
    }
}

// ---------------- fused BN normalize + (attention dots | graph pool) ----------------
__global__ void k_bn_fuse(const float* __restrict__ h, const float* __restrict__ stats,
                          const float* __restrict__ g, const float* __restrict__ b,
                          const float* __restrict__ attW,
                          float* __restrict__ x, float* __restrict__ as_, float* __restrict__ ad_,
                          const int* __restrict__ bidx, float* __restrict__ gr, int mode)
{
    int w = (blockIdx.x * blockDim.x + threadIdx.x) >> 5;
    int lane = threadIdx.x & 31;
    if (w >= NND) return;
    float4 hv = *(const float4*)(h + (size_t)w * HH + lane * 4);
    float4 s1 = *(const float4*)(stats + lane * 4);
    float4 s2 = *(const float4*)(stats + 128 + lane * 4);
    float4 gg = *(const float4*)(g + lane * 4);
    float4 bb = *(const float4*)(b + lane * 4);
    const float inv = 1.f / NND;
    float4 v;
    {
        float mu = s1.x * inv, var = s2.x * inv - mu * mu;
        v.x = (hv.x - mu) * rsqrtf(var + 1e-5f) * gg.x + bb.x;
        mu = s1.y * inv; var = s2.y * inv - mu * mu;
        v.y = (hv.y - mu) * rsqrtf(var + 1e-5f) * gg.y + bb.y;
        mu = s1.z * inv; var = s2.z * inv - mu * mu;
        v.z = (hv.z - mu) * rsqrtf(var + 1e-5f) * gg.z + bb.z;
        mu = s1.w * inv; var = s2.w * inv - mu * mu;
        v.w = (hv.w - mu) * rsqrtf(var + 1e-5f) * gg.w + bb.w;
    }
    *(float4*)(x + (size_t)w * HH + lane * 4) = v;

    if (mode == 0) {
        float4 w1 = *(const float4*)(attW + lane * 4);
        float4 w2 = *(const float4*)(attW + HH + lane * 4);
        float p1 = v.x * w1.x + v.y * w1.y + v.z * w1.z + v.w * w1.w;
        float p2 = v.x * w2.x + v.y * w2.y + v.z * w2.z + v.w * w2.w;
        #pragma unroll
        for (int o = 16; o > 0; o >>= 1) {
            p1 += __shfl_xor_sync(0xFFFFFFFFu, p1, o);
            p2 += __shfl_xor_sync(0xFFFFFFFFu, p2, o);
        }
        if (lane == 0) { as_[w] = p1; ad_[w] = p2; }
    } else {
        int gidx = __ldg(bidx + w);
        float* p = gr + (size_t)gidx * HH + lane * 4;
        asm volatile("red.global.add.v4.f32 [%0], {%1, %2, %3, %4};"
                     :: "l"(p), "f"(v.x), "f"(v.y), "f"(v.z), "f"(v.w)
                     : "memory");
    }
}

// ---------------- readout MLP ----------------
__global__ void k_readout(const float* __restrict__ gr, const float* __restrict__ W1,
                          const float* __restrict__ b1, const float* __restrict__ W2,
                          const float* __restrict__ b2, float* __restrict__ out)
{
    __shared__ float sred[64];
    int g = blockIdx.x, j = threadIdx.x;
    const float* grow = gr + (size_t)g * HH;
    const float* wrow = W1 + (size_t)j * HH;
    float acc = b1[j];
    #pragma unroll 8
    for (int k = 0; k < HH; k++) acc += grow[k] * wrow[k];
    acc = fmaxf(acc, 0.f) * W2[j];
    sred[j] = acc;
    __syncthreads();
    #pragma unroll
    for (int s = 32; s > 0; s >>= 1) {
        if (j < s) sred[j] += sred[j + s];
        __syncthreads();
    }
    if (j == 0) out[g] = sred[0] + b2[0];
}

// ---------------- host ----------------
static float* symaddrf(const void* s) { void* p = nullptr; cudaGetSymbolAddress(&p, s); return (float*)p; }
static int*   symaddri(const void* s) { void* p = nullptr; cudaGetSymbolAddress(&p, s); return (int*)p; }

extern "C" void kernel_launch(void* const* d_in, const int* in_sizes, int n_in,
                              void* d_out, int out_size)
{
    const float* nf      = (const float*)d_in[0];
    const int*   ei      = (const int*)  d_in[1];
    const int*   bidx    = (const int*)  d_in[2];
    const float* emb_W   = (const float*)d_in[3];
    const float* emb_b   = (const float*)d_in[4];
    const float* emb_g   = (const float*)d_in[5];
    const float* emb_beta= (const float*)d_in[6];
    const float* msg_W   = (const float*)d_in[7];
    const float* msg_b   = (const float*)d_in[8];
    const float* att_W   = (const float*)d_in[9];
    const float* att_b   = (const float*)d_in[10];
    const float* gru_Wih = (const float*)d_in[11];
    const float* gru_bih = (const float*)d_in[12];
    const float* gru_Whh = (const float*)d_in[13];
    const float* gru_bhh = (const float*)d_in[14];
    const float* bn_g    = (const float*)d_in[15];
    const float* bn_b    = (const float*)d_in[16];
    const float* ro_W1   = (const float*)d_in[17];
    const float* ro_b1   = (const float*)d_in[18];
    const float* ro_W2   = (const float*)d_in[19];
    const float* ro_b2   = (const float*)d_in[20];
    float* out = (float*)d_out;

    float* x    = symaddrf(g_x);
    float* h    = symaddrf(g_h);
    float* m    = symaddrf(g_m);
    float* agg  = symaddrf(g_agg);
    float* gi   = symaddrf(g_gi);
    float* gh   = symaddrf(g_gh);
    float* as_  = symaddrf(g_as);
    float* ad_  = symaddrf(g_ad);
    float* st   = symaddrf(g_stats);
    float* gr   = symaddrf(g_gr);
    float* Wpad = symaddrf(g_Wpad);
    float* Wmh  = symaddrf(g_Wmh);
    float* bmh  = symaddrf(g_bmh);
    float* Wf   = symaddrf(g_Wf);
    float* eatt = symaddrf(g_eatt);
    int* deg  = symaddri(g_deg);
    int* off  = symaddri(g_off);
    int* cur  = symaddri(g_cur);
    int* blk  = symaddri(g_blk);
    int* esrc = symaddri(g_esrc);
    int* edst = symaddri(g_edst);

    cudaFuncSetAttribute(k_gemm_tc<true>,
                         cudaFuncAttributeMaxDynamicSharedMemorySize, GSMEM_BYTES);
    cudaFuncSetAttribute(k_gemm_tc<false>,
                         cudaFuncAttributeMaxDynamicSharedMemorySize, GSMEM_BYTES);

    const int NH = NND * HH;
    const int GB = (NND + 127) / 128;    // 391 row-blocks
    dim3 gridMB(GB, 2);                  // emb GEMM (D=128)
    dim3 gridMH(GB, 8);                  // fused m+gh GEMM (D=512)
    dim3 gridGI(GB, 6);                  // gi GEMM (D=384)
    dim3 bnB(128, 8);

    // ---- setup: pads, weight packing + fragmentization, CSR build ----
    k_prep<<<(NH + 255) / 256, 256>>>(nf, emb_W, msg_W, msg_b, gru_Whh, gru_bhh,
                                      m, Wpad, Wmh, bmh);
    k_wfrag<<<NWTILES, 256>>>(Wpad, Wmh, gru_Wih, Wf);
    k_zinit<<<(NND + 255) / 256, 256>>>(deg, gr);
    k_hist<<<(NE + 255) / 256, 256>>>(ei, deg);
    k_scan1<<<NB1, 256>>>(deg, off, blk);
    k_scan2<<<1, 256>>>(blk);
    k_scan3<<<NB1, 256>>>(off, blk, cur);
    k_fill<<<(NE + 255) / 256, 256>>>(ei, cur, esrc, edst);

    // ---- embedding: GEMM+ReLU (zeroes stats), BN stats, BN+layer0 att dots ----
    k_gemm_tc<true><<<gridMB, 256, GSMEM_BYTES>>>(m, Wf, emb_b, h, h,
                                                  NND, 128, 128, 128, st);
    k_bnstats<<<256, bnB>>>(h, st);
    k_bn_fuse<<<(NND * 32 + 255) / 256, 256>>>(h, st, emb_g, emb_beta, att_W,
                                               x, as_, ad_, bidx, gr, 0);

    // ---- 4 message-passing layers ----
    for (int l = 0; l < NL; l++) {
        k_att<<<(NE + 255) / 256, 256>>>(esrc, edst, as_, ad_, att_b + l, eatt);
        // fused [m | gh] = x @ [msgW ; Whh]^T  (cols <128 -> m, >=128 -> gh)
        k_gemm_tc<false><<<gridMH, 256, GSMEM_BYTES>>>(
            x, Wf + (size_t)(2 + l * 8) * 8192, bmh + (size_t)l * 512,
            m, gh, NND, 128, 128, 384, nullptr);
        k_gather<<<(NND * 32 + 255) / 256, 256>>>(off, esrc, eatt, m, agg);
        // gi = agg @ Wih^T (zeroes stats for k_gru_bn)
        k_gemm_tc<false><<<gridGI, 256, GSMEM_BYTES>>>(
            agg, Wf + (size_t)(2 + NL * 8 + l * 6) * 8192, gru_bih + (size_t)l * 3 * HH,
            gi, gi, NND, 384, 384, 384, st);
        k_gru_bn<<<256, 256>>>(gi, gh, x, h, st);
        if (l < NL - 1) {
            k_bn_fuse<<<(NND * 32 + 255) / 256, 256>>>(
                h, st, bn_g + (size_t)l * HH, bn_b + (size_t)l * HH,
                att_W + (size_t)(l + 1) * 2 * HH, x, as_, ad_, bidx, gr, 0);
        } else {
            k_bn_fuse<<<(NND * 32 + 255) / 256, 256>>>(
                h, st, bn_g + (size_t)l * HH, bn_b + (size_t)l * HH,
                att_W, x, as_, ad_, bidx, gr, 1);
        }
    }

    // ---- readout ----
    k_readout<<<NG, 64>>>(gr, ro_W1, ro_b1, ro_W2, ro_b2, out);

    (void)in_sizes; (void)n_in; (void)out_size;
}

// round 13
// speedup vs baseline: 1.2909x; 1.2909x over previous
#include <cuda_runtime.h>
#include <cuda_fp16.h>
#include <math.h>
#include <stdint.h>

#define NND 50000
#define NE  600000
#define AD  75
#define HH  128
#define NL  4
#define NG  128
#define NB1 196   // ceil(NND/256)

#define GSMEM_BYTES (51200)       // 34816B A(fp16) + 16384B B-frag
#define NWTILES (2 + NL*8 + NL*6) // 58 weight 64-col tiles

// ---------------- scratch (static device globals; no runtime alloc) ----------------
__device__ float g_x  [NND*HH];
__device__ float g_h  [NND*HH];
__device__ float g_m  [NND*HH];
__device__ float g_agg[NND*HH];
__device__ float g_gi [NND*3*HH];
__device__ float g_gh [NND*3*HH];
__device__ float g_as [NND];
__device__ float g_ad [NND];
__device__ float g_stats[2*HH];
__device__ float g_gr [NG*HH];
__device__ float g_Wpad[HH*HH];
__device__ float g_Wmh [NL*512*HH];
__device__ float g_bmh [NL*512];
__device__ uint2 g_Wf  [NWTILES*2048];
__device__ int   g_deg [NND];
__device__ int   g_off [NND+1];
__device__ int   g_cur [NND];
__device__ int   g_blk [256];
__device__ int   g_esrc[NE];
__device__ int   g_edst[NE];
__device__ float g_eatt[NE];

__device__ __forceinline__ float sigm(float v) { return 1.f / (1.f + expf(-v)); }

__device__ __forceinline__ uint32_t cvta_smem(const void* p) {
    return (uint32_t)__cvta_generic_to_shared(p);
}

// ---------------- setup: pads + weight packing ----------------
__global__ void k_prep(const float* __restrict__ nf, const float* __restrict__ embW,
                       const float* __restrict__ msgW, const float* __restrict__ msgb,
                       const float* __restrict__ Whh, const float* __restrict__ bhh,
                       float* __restrict__ nfp, float* __restrict__ Wpad,
                       float* __restrict__ Wmh, float* __restrict__ bmh)
{
    int i = blockIdx.x * blockDim.x + threadIdx.x;
    if (i < NND * HH) {
        int n = i >> 7, c = i & 127;
        nfp[i] = (c < AD) ? nf[n * AD + c] : 0.f;
    }
    if (i < HH * HH) {
        int r = i >> 7, c = i & 127;
        Wpad[i] = (c < AD) ? embW[r * AD + c] : 0.f;
    }
    if (i < NL * 512 * HH) {
        int l = i / (512 * HH);
        int rem = i - l * 512 * HH;
        int r = rem >> 7, c = rem & 127;
        Wmh[i] = (r < HH) ? msgW[(size_t)l * HH * HH + r * HH + c]
                          : Whh[(size_t)l * 3 * HH * HH + (size_t)(r - HH) * HH + c];
    }
    if (i < NL * 512) {
        int l = i >> 9, r = i & 511;
        bmh[i] = (r < HH) ? msgb[l * HH + r] : bhh[l * 3 * HH + (r - HH)];
    }
}

// ---------------- weight fragmentization: fp16 B-fragment table per 64-col tile ----------------
// Tile layout: slot = (nt*8 + kc)*32 + lane, value = uint2{b0, b1} where
// b0 = half2(W[rbase+nt*8+lr][kc*16+2*lc], ...+1), b1 = same cols +8.
// Exactly the mma.m16n8k16.row.col fp16 B fragment for ntile nt, k-chunk kc.
__global__ void k_wfrag(const float* __restrict__ Wpad, const float* __restrict__ Wmh,
                        const float* __restrict__ Wih, uint2* __restrict__ Wf)
{
    int b = blockIdx.x;             // tile id 0..57
    const float* src; int rbase;
    if (b < 2)       { src = Wpad; rbase = b * 64; }
    else if (b < 34) { int q = b - 2;  src = Wmh + (size_t)(q >> 3) * 512 * HH; rbase = (q & 7) * 64; }
    else             { int q = b - 34; src = Wih + (size_t)(q / 6) * 3 * HH * HH; rbase = (q % 6) * 64; }
    uint2* dst = Wf + (size_t)b * 2048;
    int lane = threadIdx.x & 31;
    int lr = lane >> 2, lc = lane & 3;
    #pragma unroll
    for (int i = 0; i < 8; i++) {
        int slot = threadIdx.x + i * 256;   // 0..2047; slot&31 == lane
        int ntkc = slot >> 5;
        int kc = ntkc & 7, nt = ntkc >> 3;
        int row = rbase + nt * 8 + lr;
        int col = kc * 16 + lc * 2;
        __half2 b0 = __floats2half2_rn(src[(size_t)row * 128 + col],
                                       src[(size_t)row * 128 + col + 1]);
        __half2 b1 = __floats2half2_rn(src[(size_t)row * 128 + col + 8],
                                       src[(size_t)row * 128 + col + 9]);
        dst[slot] = make_uint2(*(uint32_t*)&b0, *(uint32_t*)&b1);
    }
}

__global__ void k_zinit(int* __restrict__ deg, float* __restrict__ gr)
{
    int i = blockIdx.x * blockDim.x + threadIdx.x;
    if (i < NND) deg[i] = 0;
    if (i < NG * HH) gr[i] = 0.f;
}

// ---------------- CSR build ----------------
__global__ void k_hist(const int* __restrict__ ei, int* __restrict__ deg)
{
    int e = blockIdx.x * blockDim.x + threadIdx.x;
    if (e < NE) atomicAdd(deg + __ldg(ei + NE + e), 1);
}

__global__ void k_scan1(const int* __restrict__ deg, int* __restrict__ off,
                        int* __restrict__ blk)
{
    __shared__ int s[256];
    int tx = threadIdx.x;
    int i = blockIdx.x * 256 + tx;
    int v = (i < NND) ? deg[i] : 0;
    s[tx] = v;
    __syncthreads();
    for (int o = 1; o < 256; o <<= 1) {
        int t = 0;
        if (tx >= o) t = s[tx - o];
        __syncthreads();
        if (tx >= o) s[tx] += t;
        __syncthreads();
    }
    if (i < NND) off[i] = s[tx] - v;
    if (tx == 255) blk[blockIdx.x] = s[255];
}

__global__ void k_scan2(int* __restrict__ blk)
{
    __shared__ int s[256];
    int tx = threadIdx.x;
    int v = (tx < NB1) ? blk[tx] : 0;
    s[tx] = v;
    __syncthreads();
    for (int o = 1; o < 256; o <<= 1) {
        int t = 0;
        if (tx >= o) t = s[tx - o];
        __syncthreads();
        if (tx >= o) s[tx] += t;
        __syncthreads();
    }
    blk[tx] = s[tx] - v;
}

__global__ void k_scan3(int* __restrict__ off, const int* __restrict__ blk,
                        int* __restrict__ cur)
{
    int i = blockIdx.x * 256 + threadIdx.x;
    if (i < NND) {
        int o = off[i] + blk[i >> 8];
        off[i] = o;
        cur[i] = o;
    }
    if (i == 0) off[NND] = NE;
}

__global__ void k_fill(const int* __restrict__ ei, int* __restrict__ cur,
                       int* __restrict__ esrc, int* __restrict__ edst)
{
    int e = blockIdx.x * blockDim.x + threadIdx.x;
    if (e >= NE) return;
    int s = __ldg(ei + e);
    int d = __ldg(ei + NE + e);
    int pos = atomicAdd(cur + d, 1);
    esrc[pos] = s;
    edst[pos] = d;
}

// ---------------- per-edge attention (CSR order) ----------------
__global__ void k_att(const int* __restrict__ esrc, const int* __restrict__ edst,
                      const float* __restrict__ as_, const float* __restrict__ ad_,
                      const float* __restrict__ attb, float* __restrict__ eatt)
{
    int p = blockIdx.x * blockDim.x + threadIdx.x;
    if (p >= NE) return;
    float a = __ldg(as_ + __ldg(esrc + p)) + __ldg(ad_ + __ldg(edst + p)) + __ldg(attb);
    eatt[p] = 1.f / (1.f + expf(-a));
}

// ---------------- gather aggregation ----------------
__global__ __launch_bounds__(256) void k_gather(
    const int* __restrict__ off, const int* __restrict__ esrc,
    const float* __restrict__ eatt, const float* __restrict__ m,
    float* __restrict__ agg)
{
    int n = (blockIdx.x * blockDim.x + threadIdx.x) >> 5;
    int lane = threadIdx.x & 31;
    if (n >= NND) return;
    int p = __ldg(off + n);
    int e = __ldg(off + n + 1);
    float4 acc = make_float4(0.f, 0.f, 0.f, 0.f);
    for (; p + 1 < e; p += 2) {
        int s0 = __ldg(esrc + p);
        int s1 = __ldg(esrc + p + 1);
        float a0 = __ldg(eatt + p);
        float a1 = __ldg(eatt + p + 1);
        float4 v0 = *(const float4*)(m + (size_t)s0 * HH + lane * 4);
        float4 v1 = *(const float4*)(m + (size_t)s1 * HH + lane * 4);
        acc.x += v0.x * a0 + v1.x * a1;
        acc.y += v0.y * a0 + v1.y * a1;
        acc.z += v0.z * a0 + v1.z * a1;
        acc.w += v0.w * a0 + v1.w * a1;
    }
    if (p < e) {
        int s0 = __ldg(esrc + p);
        float a0 = __ldg(eatt + p);
        float4 v0 = *(const float4*)(m + (size_t)s0 * HH + lane * 4);
        acc.x += v0.x * a0; acc.y += v0.y * a0;
        acc.z += v0.z * a0; acc.w += v0.w * a0;
    }
    *(float4*)(agg + (size_t)n * HH + lane * 4) = acc;
}

// ---------------- fp16 mma.sync GEMM (m16n8k16 + ldmatrix) ----------------
// C[M, 64*gridDim.y] = A[M,128] @ W^T + bias. Block tile 128x64, 8 warps (4m x 2n),
// warp tile 32x32 = 2 mtiles x 4 ntiles. A staged coalesced f32->fp16 into smem
// (row stride 136 halves -> ldmatrix conflict-free); B fragments precomputed.
// Output cols < split -> C1 (stride s1), >= split -> C2 at col-split (stride s2).
template <bool RELU>
__global__ __launch_bounds__(256) void k_gemm_tc(
    const float* __restrict__ A, const uint2* __restrict__ Wf,
    const float* __restrict__ bias, float* __restrict__ C1, float* __restrict__ C2,
    int M, int split, int s1, int s2, float* zbuf)
{
    extern __shared__ char smraw[];
    __half* AS = (__half*)smraw;               // 128 x 136 halves = 34816 B
    uint2* BF  = (uint2*)(smraw + 34816);      // 2048 uint2 = 16384 B
    const int tid = threadIdx.x;
    if (zbuf != nullptr && blockIdx.x == 0 && blockIdx.y == 0)
        zbuf[tid] = 0.f;
    const int m0 = blockIdx.x * 128;
    const int n0 = blockIdx.y * 64;
    const int lane = tid & 31;
    const int wid = tid >> 5;
    const int lr = lane >> 2;
    const int lc = lane & 3;

    // stage B: linear copy of precomputed fragment tile
    {
        const uint2* src = Wf + (size_t)blockIdx.y * 2048;
        #pragma unroll
        for (int i = 0; i < 8; i++)
            BF[tid + i * 256] = src[tid + i * 256];
    }
    // stage A: coalesced f32 load -> fp16 smem
    #pragma unroll
    for (int i = 0; i < 16; i++) {
        int idx = tid + i * 256;
        int row = idx >> 5, q = idx & 31;
        float4 v = make_float4(0.f, 0.f, 0.f, 0.f);
        if (m0 + row < M)
            v = *(const float4*)(A + (size_t)(m0 + row) * 128 + q * 4);
        __half2 h01 = __floats2half2_rn(v.x, v.y);
        __half2 h23 = __floats2half2_rn(v.z, v.w);
        *(uint2*)(AS + row * 136 + q * 4) =
            make_uint2(*(uint32_t*)&h01, *(uint32_t*)&h23);
    }
    __syncthreads();

    const int wm = (wid & 3) * 32;    // warp m base (rows)
    const int wn = (wid >> 2) * 4;    // warp n base (ntiles)
    // ldmatrix per-lane addresses (x4: quads cover m0-7/m8-15 x k0-7/k8-15)
    const int arow = wm + (lane & 7) + ((lane >> 3) & 1) * 8;
    const int acol = ((lane >> 4) & 1) * 8;
    const uint32_t abase0 = cvta_smem(AS + arow * 136 + acol);
    const uint32_t abase1 = cvta_smem(AS + (arow + 16) * 136 + acol);

    float acc[2][4][4];
    #pragma unroll
    for (int i = 0; i < 2; i++)
        #pragma unroll
        for (int j = 0; j < 4; j++)
            #pragma unroll
            for (int q = 0; q < 4; q++) acc[i][j][q] = 0.f;

    #pragma unroll
    for (int kc = 0; kc < 8; kc++) {
        uint32_t a[2][4];
        asm volatile("ldmatrix.sync.aligned.m8n8.x4.shared.b16 {%0,%1,%2,%3}, [%4];"
                     : "=r"(a[0][0]), "=r"(a[0][1]), "=r"(a[0][2]), "=r"(a[0][3])
                     : "r"(abase0 + kc * 32));
        asm volatile("ldmatrix.sync.aligned.m8n8.x4.shared.b16 {%0,%1,%2,%3}, [%4];"
                     : "=r"(a[1][0]), "=r"(a[1][1]), "=r"(a[1][2]), "=r"(a[1][3])
                     : "r"(abase1 + kc * 32));
        uint2 b[4];
        #pragma unroll
        for (int nt = 0; nt < 4; nt++)
            b[nt] = BF[((wn + nt) * 8 + kc) * 32 + lane];
        #pragma unroll
        for (int mt = 0; mt < 2; mt++)
            #pragma unroll
            for (int nt = 0; nt < 4; nt++) {
                asm volatile(
                    "mma.sync.aligned.m16n8k16.row.col.f32.f16.f16.f32 "
                    "{%0,%1,%2,%3}, {%4,%5,%6,%7}, {%8,%9}, {%0,%1,%2,%3};\n"
                    : "+f"(acc[mt][nt][0]), "+f"(acc[mt][nt][1]),
                      "+f"(acc[mt][nt][2]), "+f"(acc[mt][nt][3])
                    : "r"(a[mt][0]), "r"(a[mt][1]), "r"(a[mt][2]), "r"(a[mt][3]),
                      "r"(b[nt].x), "r"(b[nt].y));
            }
    }

    // epilogue
    float* Cp; int cstr, coff;
    if (n0 < split) { Cp = C1; cstr = s1; coff = 0; }
    else            { Cp = C2; cstr = s2; coff = split; }
    #pragma unroll
    for (int mt = 0; mt < 2; mt++) {
        #pragma unroll
        for (int nt = 0; nt < 4; nt++) {
            int cb = n0 + (wn + nt) * 8 + lc * 2;
            float2 bv = *(const float2*)(bias + cb);
            int cc = cb - coff;
            int r0 = m0 + wm + mt * 16 + lr;
            if (r0 < M) {
                float2 o;
                o.x = acc[mt][nt][0] + bv.x;
                o.y = acc[mt][nt][1] + bv.y;
                if (RELU) { o.x = fmaxf(o.x, 0.f); o.y = fmaxf(o.y, 0.f); }
                *(float2*)(Cp + (size_t)r0 * cstr + cc) = o;
            }
            int r1 = r0 + 8;
            if (r1 < M) {
                float2 o;
                o.x = acc[mt][nt][2] + bv.x;
                o.y = acc[mt][nt][3] + bv.y;
                if (RELU) { o.x = fmaxf(o.x, 0.f); o.y = fmaxf(o.y, 0.f); }
                *(float2*)(Cp + (size_t)r1 * cstr + cc) = o;
            }
        }
    }
}

// ---------------- fused GRU elementwise + BN stats ----------------
__global__ __launch_bounds__(256) void k_gru_bn(
    const float* __restrict__ gi, const float* __restrict__ gh,
    const float* __restrict__ x, float* __restrict__ h, float* __restrict__ stats)
{
    __shared__ float ss[256];
    __shared__ float sq[256];
    int c  = threadIdx.x & 127;
    int ry = threadIdx.x >> 7;
    float s = 0.f, q = 0.f;
    for (int r = blockIdx.x * 2 + ry; r < NND; r += gridDim.x * 2) {
        const float* gin = gi + (size_t)r * 384;
        const float* ghn = gh + (size_t)r * 384;
        float rr = sigm(gin[c]       + ghn[c]);
        float zz = sigm(gin[c + 128] + ghn[c + 128]);
        float nn = tanhf(gin[c + 256] + rr * ghn[c + 256]);
        float v  = (1.f - zz) * nn + zz * x[(size_t)r * 128 + c];
        h[(size_t)r * 128 + c] = v;
        s += v; q += v * v;
    }
    ss[threadIdx.x] = s;
    sq[threadIdx.x] = q;
    __syncthreads();
    if (threadIdx.x < 128) {
        atomicAdd(stats + c, ss[threadIdx.x] + ss[threadIdx.x + 128]);
        atomicAdd(stats + 128 + c, sq[threadIdx.x] + sq[threadIdx.x + 128]);
    }
}

// ---------------- BN stats (embedding stage) ----------------
__global__ void k_bnstats(const float* __restrict__ h, float* __restrict__ stats)
{
    __shared__ float ss[8][128];
    __shared__ float sq[8][128];
    int c = threadIdx.x;
    float s = 0.f, q = 0.f;
    for (int r = blockIdx.x * 8 + threadIdx.y; r < NND; r += gridDim.x * 8) {
        float v = h[(size_t)r * 128 + c];
        s += v; q += v * v;
    }
    ss[threadIdx.y][c] = s;
    sq[threadIdx.y][c] = q;
    __syncthreads();
    if (threadIdx.y == 0) {
        #pragma unroll
        for (int y = 1; y < 8; y++) { s += ss[y][c]; q += sq[y][c]; }
        atomicAdd(stats + c, s);
        atomicAdd(stats + 128 + c, q);
    }
}

// ---------------- fused BN normalize + (attention dots | graph pool) ----------------
__global__ void k_bn_fuse(const float* __restrict__ h, const float* __restrict__ stats,
                          const float* __restrict__ g, const float* __restrict__ b,
                          const float* __restrict__ attW,
                          float* __restrict__ x, float* __restrict__ as_, float* __restrict__ ad_,
                          const int* __restrict__ bidx, float* __restrict__ gr, int mode)
{
    int w = (blockIdx.x * blockDim.x + threadIdx.x) >> 5;
    int lane = threadIdx.x & 31;
    if (w >= NND) return;
    float4 hv = *(const float4*)(h + (size_t)w * HH + lane * 4);
    float4 s1 = *(const float4*)(stats + lane * 4);
    float4 s2 = *(const float4*)(stats + 128 + lane * 4);
    float4 gg = *(const float4*)(g + lane * 4);
    float4 bb = *(const float4*)(b + lane * 4);
    const float inv = 1.f / NND;
    float4 v;
    {
        float mu = s1.x * inv, var = s2.x * inv - mu * mu;
        v.x = (hv.x - mu) * rsqrtf(var + 1e-5f) * gg.x + bb.x;
        mu = s1.y * inv; var = s2.y * inv - mu * mu;
        v.y = (hv.y - mu) * rsqrtf(var + 1e-5f) * gg.y + bb.y;
        mu = s1.z * inv; var = s2.z * inv - mu * mu;
        v.z = (hv.z - mu) * rsqrtf(var + 1e-5f) * gg.z + bb.z;
        mu = s1.w * inv; var = s2.w * inv - mu * mu;
        v.w = (hv.w - mu) * rsqrtf(var + 1e-5f) * gg.w + bb.w;
    }
    *(float4*)(x + (size_t)w * HH + lane * 4) = v;

    if (mode == 0) {
        float4 w1 = *(const float4*)(attW + lane * 4);
        float4 w2 = *(const float4*)(attW + HH + lane * 4);
        float p1 = v.x * w1.x + v.y * w1.y + v.z * w1.z + v.w * w1.w;
        float p2 = v.x * w2.x + v.y * w2.y + v.z * w2.z + v.w * w2.w;
        #pragma unroll
        for (int o = 16; o > 0; o >>= 1) {
            p1 += __shfl_xor_sync(0xFFFFFFFFu, p1, o);
            p2 += __shfl_xor_sync(0xFFFFFFFFu, p2, o);
        }
        if (lane == 0) { as_[w] = p1; ad_[w] = p2; }
    } else {
        int gidx = __ldg(bidx + w);
        float* p = gr + (size_t)gidx * HH + lane * 4;
        asm volatile("red.global.add.v4.f32 [%0], {%1, %2, %3, %4};"
                     :: "l"(p), "f"(v.x), "f"(v.y), "f"(v.z), "f"(v.w)
                     : "memory");
    }
}

// ---------------- readout MLP ----------------
__global__ void k_readout(const float* __restrict__ gr, const float* __restrict__ W1,
                          const float* __restrict__ b1, const float* __restrict__ W2,
                          const float* __restrict__ b2, float* __restrict__ out)
{
    __shared__ float sred[64];
    int g = blockIdx.x, j = threadIdx.x;
    const float* grow = gr + (size_t)g * HH;
    const float* wrow = W1 + (size_t)j * HH;
    float acc = b1[j];
    #pragma unroll 8
    for (int k = 0; k < HH; k++) acc += grow[k] * wrow[k];
    acc = fmaxf(acc, 0.f) * W2[j];
    sred[j] = acc;
    __syncthreads();
    #pragma unroll
    for (int s = 32; s > 0; s >>= 1) {
        if (j < s) sred[j] += sred[j + s];
        __syncthreads();
    }
    if (j == 0) out[g] = sred[0] + b2[0];
}

// ---------------- host ----------------
static float* symaddrf(const void* s) { void* p = nullptr; cudaGetSymbolAddress(&p, s); return (float*)p; }
static int*   symaddri(const void* s) { void* p = nullptr; cudaGetSymbolAddress(&p, s); return (int*)p; }

extern "C" void kernel_launch(void* const* d_in, const int* in_sizes, int n_in,
                              void* d_out, int out_size)
{
    const float* nf      = (const float*)d_in[0];
    const int*   ei      = (const int*)  d_in[1];
    const int*   bidx    = (const int*)  d_in[2];
    const float* emb_W   = (const float*)d_in[3];
    const float* emb_b   = (const float*)d_in[4];
    const float* emb_g   = (const float*)d_in[5];
    const float* emb_beta= (const float*)d_in[6];
    const float* msg_W   = (const float*)d_in[7];
    const float* msg_b   = (const float*)d_in[8];
    const float* att_W   = (const float*)d_in[9];
    const float* att_b   = (const float*)d_in[10];
    const float* gru_Wih = (const float*)d_in[11];
    const float* gru_bih = (const float*)d_in[12];
    const float* gru_Whh = (const float*)d_in[13];
    const float* gru_bhh = (const float*)d_in[14];
    const float* bn_g    = (const float*)d_in[15];
    const float* bn_b    = (const float*)d_in[16];
    const float* ro_W1   = (const float*)d_in[17];
    const float* ro_b1   = (const float*)d_in[18];
    const float* ro_W2   = (const float*)d_in[19];
    const float* ro_b2   = (const float*)d_in[20];
    float* out = (float*)d_out;

    float* x    = symaddrf(g_x);
    float* h    = symaddrf(g_h);
    float* m    = symaddrf(g_m);
    float* agg  = symaddrf(g_agg);
    float* gi   = symaddrf(g_gi);
    float* gh   = symaddrf(g_gh);
    float* as_  = symaddrf(g_as);
    float* ad_  = symaddrf(g_ad);
    float* st   = symaddrf(g_stats);
    float* gr   = symaddrf(g_gr);
    float* Wpad = symaddrf(g_Wpad);
    float* Wmh  = symaddrf(g_Wmh);
    float* bmh  = symaddrf(g_bmh);
    uint2* Wf   = (uint2*)symaddrf(g_Wf);
    float* eatt = symaddrf(g_eatt);
    int* deg  = symaddri(g_deg);
    int* off  = symaddri(g_off);
    int* cur  = symaddri(g_cur);
    int* blk  = symaddri(g_blk);
    int* esrc = symaddri(g_esrc);
    int* edst = symaddri(g_edst);

    cudaFuncSetAttribute(k_gemm_tc<true>,
                         cudaFuncAttributeMaxDynamicSharedMemorySize, GSMEM_BYTES);
    cudaFuncSetAttribute(k_gemm_tc<false>,
                         cudaFuncAttributeMaxDynamicSharedMemorySize, GSMEM_BYTES);

    const int NH = NND * HH;
    const int GB = (NND + 127) / 128;    // 391 row-blocks
    dim3 gridMB(GB, 2);                  // emb GEMM (D=128)
    dim3 gridMH(GB, 8);                  // fused m+gh GEMM (D=512)
    dim3 gridGI(GB, 6);                  // gi GEMM (D=384)
    dim3 bnB(128, 8);

    // ---- setup: pads, weight packing + fragmentization, CSR build ----
    k_prep<<<(NH + 255) / 256, 256>>>(nf, emb_W, msg_W, msg_b, gru_Whh, gru_bhh,
                                      m, Wpad, Wmh, bmh);
    k_wfrag<<<NWTILES, 256>>>(Wpad, Wmh, gru_Wih, Wf);
    k_zinit<<<(NND + 255) / 256, 256>>>(deg, gr);
    k_hist<<<(NE + 255) / 256, 256>>>(ei, deg);
    k_scan1<<<NB1, 256>>>(deg, off, blk);
    k_scan2<<<1, 256>>>(blk);
    k_scan3<<<NB1, 256>>>(off, blk, cur);
    k_fill<<<(NE + 255) / 256, 256>>>(ei, cur, esrc, edst);

    // ---- embedding: GEMM+ReLU (zeroes stats), BN stats, BN+layer0 att dots ----
    k_gemm_tc<true><<<gridMB, 256, GSMEM_BYTES>>>(m, Wf, emb_b, h, h,
                                                  NND, 128, 128, 128, st);
    k_bnstats<<<256, bnB>>>(h, st);
    k_bn_fuse<<<(NND * 32 + 255) / 256, 256>>>(h, st, emb_g, emb_beta, att_W,
                                               x, as_, ad_, bidx, gr, 0);

    // ---- 4 message-passing layers ----
    for (int l = 0; l < NL; l++) {
        k_att<<<(NE + 255) / 256, 256>>>(esrc, edst, as_, ad_, att_b + l, eatt);
        // fused [m | gh] = x @ [msgW ; Whh]^T  (cols <128 -> m, >=128 -> gh)
        k_gemm_tc<false><<<gridMH, 256, GSMEM_BYTES>>>(
            x, Wf + (size_t)(2 + l * 8) * 2048, bmh + (size_t)l * 512,
            m, gh, NND, 128, 128, 384, nullptr);
        k_gather<<<(NND * 32 + 255) / 256, 256>>>(off, esrc, eatt, m, agg);
        // gi = agg @ Wih^T (zeroes stats for k_gru_bn)
        k_gemm_tc<false><<<gridGI, 256, GSMEM_BYTES>>>(
            agg, Wf + (size_t)(2 + NL * 8 + l * 6) * 2048, gru_bih + (size_t)l * 3 * HH,
            gi, gi, NND, 384, 384, 384, st);
        k_gru_bn<<<256, 256>>>(gi, gh, x, h, st);
        if (l < NL - 1) {
            k_bn_fuse<<<(NND * 32 + 255) / 256, 256>>>(
                h, st, bn_g + (size_t)l * HH, bn_b + (size_t)l * HH,
                att_W + (size_t)(l + 1) * 2 * HH, x, as_, ad_, bidx, gr, 0);
        } else {
            k_bn_fuse<<<(NND * 32 + 255) / 256, 256>>>(
                h, st, bn_g + (size_t)l * HH, bn_b + (size_t)l * HH,
                att_W, x, as_, ad_, bidx, gr, 1);
        }
    }

    // ---- readout ----
    k_readout<<<NG, 64>>>(gr, ro_W1, ro_b1, ro_W2, ro_b2, out);

    (void)in_sizes; (void)n_in; (void)out_size;
}

// round 14
// speedup vs baseline: 1.3015x; 1.0082x over previous
#include <cuda_runtime.h>
#include <cuda_fp16.h>
#include <math.h>
#include <stdint.h>

#define NND 50000
#define NE  600000
#define AD  75
#define HH  128
#define NL  4
#define NG  128
#define NB1 196   // ceil(NND/256)

#define GSMEM_BYTES (34816 + 32768)   // A fp16 (128x136) + 2 B-frag tiles
#define NWTILES (2 + NL*8 + NL*6)     // 58 weight 64-col tiles

// ---------------- scratch (static device globals; no runtime alloc) ----------------
__device__ float g_x  [NND*HH];
__device__ float g_h  [NND*HH];
__device__ float g_m  [NND*HH];
__device__ float g_agg[NND*HH];
__device__ float g_gi [NND*3*HH];
__device__ float g_gh [NND*3*HH];
__device__ float g_as [NND];
__device__ float g_ad [NND];
__device__ float g_stats[2*HH];
__device__ float g_gr [NG*HH];
__device__ float g_Wpad[HH*HH];
__device__ float g_Wmh [NL*512*HH];
__device__ float g_bmh [NL*512];
__device__ uint2 g_Wf  [NWTILES*2048];
__device__ int   g_deg [NND];
__device__ int   g_off [NND+1];
__device__ int   g_cur [NND];
__device__ int   g_blk [256];
__device__ int   g_esrc[NE];

__device__ __forceinline__ float sigm(float v) { return 1.f / (1.f + expf(-v)); }

__device__ __forceinline__ uint32_t cvta_smem(const void* p) {
    return (uint32_t)__cvta_generic_to_shared(p);
}

// ---------------- setup: pads + weight packing ----------------
__global__ void k_prep(const float* __restrict__ nf, const float* __restrict__ embW,
                       const float* __restrict__ msgW, const float* __restrict__ msgb,
                       const float* __restrict__ Whh, const float* __restrict__ bhh,
                       float* __restrict__ nfp, float* __restrict__ Wpad,
                       float* __restrict__ Wmh, float* __restrict__ bmh)
{
    int i = blockIdx.x * blockDim.x + threadIdx.x;
    if (i < NND * HH) {
        int n = i >> 7, c = i & 127;
        nfp[i] = (c < AD) ? nf[n * AD + c] : 0.f;
    }
    if (i < HH * HH) {
        int r = i >> 7, c = i & 127;
        Wpad[i] = (c < AD) ? embW[r * AD + c] : 0.f;
    }
    if (i < NL * 512 * HH) {
        int l = i / (512 * HH);
        int rem = i - l * 512 * HH;
        int r = rem >> 7, c = rem & 127;
        Wmh[i] = (r < HH) ? msgW[(size_t)l * HH * HH + r * HH + c]
                          : Whh[(size_t)l * 3 * HH * HH + (size_t)(r - HH) * HH + c];
    }
    if (i < NL * 512) {
        int l = i >> 9, r = i & 511;
        bmh[i] = (r < HH) ? msgb[l * HH + r] : bhh[l * 3 * HH + (r - HH)];
    }
}

// ---------------- weight fragmentization: fp16 B-fragment table per 64-col tile ----------------
__global__ void k_wfrag(const float* __restrict__ Wpad, const float* __restrict__ Wmh,
                        const float* __restrict__ Wih, uint2* __restrict__ Wf)
{
    int b = blockIdx.x;             // tile id 0..57
    const float* src; int rbase;
    if (b < 2)       { src = Wpad; rbase = b * 64; }
    else if (b < 34) { int q = b - 2;  src = Wmh + (size_t)(q >> 3) * 512 * HH; rbase = (q & 7) * 64; }
    else             { int q = b - 34; src = Wih + (size_t)(q / 6) * 3 * HH * HH; rbase = (q % 6) * 64; }
    uint2* dst = Wf + (size_t)b * 2048;
    int lane = threadIdx.x & 31;
    int lr = lane >> 2, lc = lane & 3;
    #pragma unroll
    for (int i = 0; i < 8; i++) {
        int slot = threadIdx.x + i * 256;   // 0..2047; slot&31 == lane
        int ntkc = slot >> 5;
        int kc = ntkc & 7, nt = ntkc >> 3;
        int row = rbase + nt * 8 + lr;
        int col = kc * 16 + lc * 2;
        __half2 b0 = __floats2half2_rn(src[(size_t)row * 128 + col],
                                       src[(size_t)row * 128 + col + 1]);
        __half2 b1 = __floats2half2_rn(src[(size_t)row * 128 + col + 8],
                                       src[(size_t)row * 128 + col + 9]);
        dst[slot] = make_uint2(*(uint32_t*)&b0, *(uint32_t*)&b1);
    }
}

__global__ void k_zinit(int* __restrict__ deg, float* __restrict__ gr)
{
    int i = blockIdx.x * blockDim.x + threadIdx.x;
    if (i < NND) deg[i] = 0;
    if (i < NG * HH) gr[i] = 0.f;
}

// ---------------- CSR build ----------------
__global__ void k_hist(const int* __restrict__ ei, int* __restrict__ deg)
{
    int e = blockIdx.x * blockDim.x + threadIdx.x;
    if (e < NE) atomicAdd(deg + __ldg(ei + NE + e), 1);
}

__global__ void k_scan1(const int* __restrict__ deg, int* __restrict__ off,
                        int* __restrict__ blk)
{
    __shared__ int s[256];
    int tx = threadIdx.x;
    int i = blockIdx.x * 256 + tx;
    int v = (i < NND) ? deg[i] : 0;
    s[tx] = v;
    __syncthreads();
    for (int o = 1; o < 256; o <<= 1) {
        int t = 0;
        if (tx >= o) t = s[tx - o];
        __syncthreads();
        if (tx >= o) s[tx] += t;
        __syncthreads();
    }
    if (i < NND) off[i] = s[tx] - v;
    if (tx == 255) blk[blockIdx.x] = s[255];
}

__global__ void k_scan2(int* __restrict__ blk)
{
    __shared__ int s[256];
    int tx = threadIdx.x;
    int v = (tx < NB1) ? blk[tx] : 0;
    s[tx] = v;
    __syncthreads();
    for (int o = 1; o < 256; o <<= 1) {
        int t = 0;
        if (tx >= o) t = s[tx - o];
        __syncthreads();
        if (tx >= o) s[tx] += t;
        __syncthreads();
    }
    blk[tx] = s[tx] - v;
}

__global__ void k_scan3(int* __restrict__ off, const int* __restrict__ blk,
                        int* __restrict__ cur)
{
    int i = blockIdx.x * 256 + threadIdx.x;
    if (i < NND) {
        int o = off[i] + blk[i >> 8];
        off[i] = o;
        cur[i] = o;
    }
    if (i == 0) off[NND] = NE;
}

__global__ void k_fill(const int* __restrict__ ei, int* __restrict__ cur,
                       int* __restrict__ esrc)
{
    int e = blockIdx.x * blockDim.x + threadIdx.x;
    if (e >= NE) return;
    int s = __ldg(ei + e);
    int d = __ldg(ei + NE + e);
    int pos = atomicAdd(cur + d, 1);
    esrc[pos] = s;
}

// ---------------- gather aggregation with inline attention ----------------
// agg[n] = sum_{e in CSR(n)} m[src[e]] * sigmoid(as[src[e]] + ad[n] + attb)
__global__ __launch_bounds__(256) void k_gather(
    const int* __restrict__ off, const int* __restrict__ esrc,
    const float* __restrict__ as_, const float* __restrict__ ad_,
    const float* __restrict__ attb, const float* __restrict__ m,
    float* __restrict__ agg)
{
    int n = (blockIdx.x * blockDim.x + threadIdx.x) >> 5;
    int lane = threadIdx.x & 31;
    if (n >= NND) return;
    int p = __ldg(off + n);
    int e = __ldg(off + n + 1);
    float adn = __ldg(ad_ + n) + __ldg(attb);
    float4 acc = make_float4(0.f, 0.f, 0.f, 0.f);
    for (; p + 1 < e; p += 2) {
        int s0 = __ldg(esrc + p);
        int s1 = __ldg(esrc + p + 1);
        float a0 = sigm(__ldg(as_ + s0) + adn);
        float a1 = sigm(__ldg(as_ + s1) + adn);
        float4 v0 = *(const float4*)(m + (size_t)s0 * HH + lane * 4);
        float4 v1 = *(const float4*)(m + (size_t)s1 * HH + lane * 4);
        acc.x += v0.x * a0 + v1.x * a1;
        acc.y += v0.y * a0 + v1.y * a1;
        acc.z += v0.z * a0 + v1.z * a1;
        acc.w += v0.w * a0 + v1.w * a1;
    }
    if (p < e) {
        int s0 = __ldg(esrc + p);
        float a0 = sigm(__ldg(as_ + s0) + adn);
        float4 v0 = *(const float4*)(m + (size_t)s0 * HH + lane * 4);
        acc.x += v0.x * a0; acc.y += v0.y * a0;
        acc.z += v0.z * a0; acc.w += v0.w * a0;
    }
    *(float4*)(agg + (size_t)n * HH + lane * 4) = acc;
}

// ---------------- fp16 mma.sync GEMM (m16n8k16 + ldmatrix), 128x128 block tile ----------------
// C[M, 128*gridDim.y] = A[M,128] @ W^T + bias. 8 warps = 4m x 2n; warp tile
// 32 x 64 = 2 mtiles x 8 ntiles. A staged f32->fp16 (stride 136 -> ldmatrix
// conflict-free); 2 precomputed B-fragment tiles copied linearly.
// Output cols < split -> C1 (stride s1), >= split -> C2 at col-split (stride s2).
template <bool RELU>
__global__ __launch_bounds__(256) void k_gemm_tc(
    const float* __restrict__ A, const uint2* __restrict__ Wf,
    const float* __restrict__ bias, float* __restrict__ C1, float* __restrict__ C2,
    int M, int split, int s1, int s2, float* zbuf)
{
    extern __shared__ char smraw[];
    __half* AS = (__half*)smraw;               // 128 x 136 halves = 34816 B
    uint2* BF  = (uint2*)(smraw + 34816);      // 4096 uint2 = 32768 B (2 tiles)
    const int tid = threadIdx.x;
    if (zbuf != nullptr && blockIdx.x == 0 && blockIdx.y == 0)
        zbuf[tid] = 0.f;
    const int m0 = blockIdx.x * 128;
    const int n0 = blockIdx.y * 128;
    const int lane = tid & 31;
    const int wid = tid >> 5;
    const int lr = lane >> 2;
    const int lc = lane & 3;

    // stage B: linear copy of 2 precomputed fragment tiles
    {
        const uint2* src = Wf + (size_t)blockIdx.y * 4096;
        #pragma unroll
        for (int i = 0; i < 16; i++)
            BF[tid + i * 256] = src[tid + i * 256];
    }
    // stage A: coalesced f32 load -> fp16 smem
    #pragma unroll
    for (int i = 0; i < 16; i++) {
        int idx = tid + i * 256;
        int row = idx >> 5, q = idx & 31;
        float4 v = make_float4(0.f, 0.f, 0.f, 0.f);
        if (m0 + row < M)
            v = *(const float4*)(A + (size_t)(m0 + row) * 128 + q * 4);
        __half2 h01 = __floats2half2_rn(v.x, v.y);
        __half2 h23 = __floats2half2_rn(v.z, v.w);
        *(uint2*)(AS + row * 136 + q * 4) =
            make_uint2(*(uint32_t*)&h01, *(uint32_t*)&h23);
    }
    __syncthreads();

    const int wm = (wid & 3) * 32;      // warp m base (rows)
    const int wt = wid >> 2;            // warp n half (0/1): ntiles wt*8..wt*8+7
    const uint2* BW = BF + wt * 2048;
    const int arow = wm + (lane & 7) + ((lane >> 3) & 1) * 8;
    const int acol = ((lane >> 4) & 1) * 8;
    const uint32_t abase0 = cvta_smem(AS + arow * 136 + acol);
    const uint32_t abase1 = cvta_smem(AS + (arow + 16) * 136 + acol);

    float acc[2][8][4];
    #pragma unroll
    for (int i = 0; i < 2; i++)
        #pragma unroll
        for (int j = 0; j < 8; j++)
            #pragma unroll
            for (int q = 0; q < 4; q++) acc[i][j][q] = 0.f;

    #pragma unroll
    for (int kc = 0; kc < 8; kc++) {
        uint32_t a[2][4];
        asm volatile("ldmatrix.sync.aligned.m8n8.x4.shared.b16 {%0,%1,%2,%3}, [%4];"
                     : "=r"(a[0][0]), "=r"(a[0][1]), "=r"(a[0][2]), "=r"(a[0][3])
                     : "r"(abase0 + kc * 32));
        asm volatile("ldmatrix.sync.aligned.m8n8.x4.shared.b16 {%0,%1,%2,%3}, [%4];"
                     : "=r"(a[1][0]), "=r"(a[1][1]), "=r"(a[1][2]), "=r"(a[1][3])
                     : "r"(abase1 + kc * 32));
        uint2 b[8];
        #pragma unroll
        for (int j = 0; j < 8; j++)
            b[j] = BW[(j * 8 + kc) * 32 + lane];
        #pragma unroll
        for (int mt = 0; mt < 2; mt++)
            #pragma unroll
            for (int j = 0; j < 8; j++) {
                asm volatile(
                    "mma.sync.aligned.m16n8k16.row.col.f32.f16.f16.f32 "
                    "{%0,%1,%2,%3}, {%4,%5,%6,%7}, {%8,%9}, {%0,%1,%2,%3};\n"
                    : "+f"(acc[mt][j][0]), "+f"(acc[mt][j][1]),
                      "+f"(acc[mt][j][2]), "+f"(acc[mt][j][3])
                    : "r"(a[mt][0]), "r"(a[mt][1]), "r"(a[mt][2]), "r"(a[mt][3]),
                      "r"(b[j].x), "r"(b[j].y));
            }
    }

    // epilogue
    float* Cp; int cstr, coff;
    if (n0 < split) { Cp = C1; cstr = s1; coff = 0; }
    else            { Cp = C2; cstr = s2; coff = split; }
    #pragma unroll
    for (int mt = 0; mt < 2; mt++) {
        #pragma unroll
        for (int j = 0; j < 8; j++) {
            int cb = n0 + (wt * 8 + j) * 8 + lc * 2;
            float2 bv = *(const float2*)(bias + cb);
            int cc = cb - coff;
            int r0 = m0 + wm + mt * 16 + lr;
            if (r0 < M) {
                float2 o;
                o.x = acc[mt][j][0] + bv.x;
                o.y = acc[mt][j][1] + bv.y;
                if (RELU) { o.x = fmaxf(o.x, 0.f); o.y = fmaxf(o.y, 0.f); }
                *(float2*)(Cp + (size_t)r0 * cstr + cc) = o;
            }
            int r1 = r0 + 8;
            if (r1 < M) {
                float2 o;
                o.x = acc[mt][j][2] + bv.x;
                o.y = acc[mt][j][3] + bv.y;
                if (RELU) { o.x = fmaxf(o.x, 0.f); o.y = fmaxf(o.y, 0.f); }
                *(float2*)(Cp + (size_t)r1 * cstr + cc) = o;
            }
        }
    }
}

// ---------------- fused GRU elementwise + BN stats ----------------
__global__ __launch_bounds__(256) void k_gru_bn(
    const float* __restrict__ gi, const float* __restrict__ gh,
    const float* __restrict__ x, float* __restrict__ h, float* __restrict__ stats)
{
    __shared__ float ss[256];
    __shared__ float sq[256];
    int c  = threadIdx.x & 127;
    int ry = threadIdx.x >> 7;
    float s = 0.f, q = 0.f;
    for (int r = blockIdx.x * 2 + ry; r < NND; r += gridDim.x * 2) {
        const float* gin = gi + (size_t)r * 384;
        const float* ghn = gh + (size_t)r * 384;
        float rr = sigm(gin[c]       + ghn[c]);
        float zz = sigm(gin[c + 128] + ghn[c + 128]);
        float nn = tanhf(gin[c + 256] + rr * ghn[c + 256]);
        float v  = (1.f - zz) * nn + zz * x[(size_t)r * 128 + c];
        h[(size_t)r * 128 + c] = v;
        s += v; q += v * v;
    }
    ss[threadIdx.x] = s;
    sq[threadIdx.x] = q;
    __syncthreads();
    if (threadIdx.x < 128) {
        atomicAdd(stats + c, ss[threadIdx.x] + ss[threadIdx.x + 128]);
        atomicAdd(stats + 128 + c, sq[threadIdx.x] + sq[threadIdx.x + 128]);
    }
}

// ---------------- BN stats (embedding stage) ----------------
__global__ void k_bnstats(const float* __restrict__ h, float* __restrict__ stats)
{
    __shared__ float ss[8][128];
    __shared__ float sq[8][128];
    int c = threadIdx.x;
    float s = 0.f, q = 0.f;
    for (int r = blockIdx.x * 8 + threadIdx.y; r < NND; r += gridDim.x * 8) {
        float v = h[(size_t)r * 128 + c];
        s += v; q += v * v;
    }
    ss[threadIdx.y][c] = s;
    sq[threadIdx.y][c] = q;
    __syncthreads();
    if (threadIdx.y == 0) {
        #pragma unroll
        for (int y = 1; y < 8; y++) { s += ss[y][c]; q += sq[y][c]; }
        atomicAdd(stats + c, s);
        atomicAdd(stats + 128 + c, q);
    }
}

// ---------------- fused BN normalize + (attention dots | graph pool) ----------------
__global__ void k_bn_fuse(const float* __restrict__ h, const float* __restrict__ stats,
                          const float* __restrict__ g, const float* __restrict__ b,
                          const float* __restrict__ attW,
                          float* __restrict__ x, float* __restrict__ as_, float* __restrict__ ad_,
                          const int* __restrict__ bidx, float* __restrict__ gr, int mode)
{
    int w = (blockIdx.x * blockDim.x + threadIdx.x) >> 5;
    int lane = threadIdx.x & 31;
    if (w >= NND) return;
    float4 hv = *(const float4*)(h + (size_t)w * HH + lane * 4);
    float4 s1 = *(const float4*)(stats + lane * 4);
    float4 s2 = *(const float4*)(stats + 128 + lane * 4);
    float4 gg = *(const float4*)(g + lane * 4);
    float4 bb = *(const float4*)(b + lane * 4);
    const float inv = 1.f / NND;
    float4 v;
    {
        float mu = s1.x * inv, var = s2.x * inv - mu * mu;
        v.x = (hv.x - mu) * rsqrtf(var + 1e-5f) * gg.x + bb.x;
        mu = s1.y * inv; var = s2.y * inv - mu * mu;
        v.y = (hv.y - mu) * rsqrtf(var + 1e-5f) * gg.y + bb.y;
        mu = s1.z * inv; var = s2.z * inv - mu * mu;
        v.z = (hv.z - mu) * rsqrtf(var + 1e-5f) * gg.z + bb.z;
        mu = s1.w * inv; var = s2.w * inv - mu * mu;
        v.w = (hv.w - mu) * rsqrtf(var + 1e-5f) * gg.w + bb.w;
    }
    *(float4*)(x + (size_t)w * HH + lane * 4) = v;

    if (mode == 0) {
        float4 w1 = *(const float4*)(attW + lane * 4);
        float4 w2 = *(const float4*)(attW + HH + lane * 4);
        float p1 = v.x * w1.x + v.y * w1.y + v.z * w1.z + v.w * w1.w;
        float p2 = v.x * w2.x + v.y * w2.y + v.z * w2.z + v.w * w2.w;
        #pragma unroll
        for (int o = 16; o > 0; o >>= 1) {
            p1 += __shfl_xor_sync(0xFFFFFFFFu, p1, o);
            p2 += __shfl_xor_sync(0xFFFFFFFFu, p2, o);
        }
        if (lane == 0) { as_[w] = p1; ad_[w] = p2; }
    } else {
        int gidx = __ldg(bidx + w);
        float* p = gr + (size_t)gidx * HH + lane * 4;
        asm volatile("red.global.add.v4.f32 [%0], {%1, %2, %3, %4};"
                     :: "l"(p), "f"(v.x), "f"(v.y), "f"(v.z), "f"(v.w)
                     : "memory");
    }
}

// ---------------- readout MLP ----------------
__global__ void k_readout(const float* __restrict__ gr, const float* __restrict__ W1,
                          const float* __restrict__ b1, const float* __restrict__ W2,
                          const float* __restrict__ b2, float* __restrict__ out)
{
    __shared__ float sred[64];
    int g = blockIdx.x, j = threadIdx.x;
    const float* grow = gr + (size_t)g * HH;
    const float* wrow = W1 + (size_t)j * HH;
    float acc = b1[j];
    #pragma unroll 8
    for (int k = 0; k < HH; k++) acc += grow[k] * wrow[k];
    acc = fmaxf(acc, 0.f) * W2[j];
    sred[j] = acc;
    __syncthreads();
    #pragma unroll
    for (int s = 32; s > 0; s >>= 1) {
        if (j < s) sred[j] += sred[j + s];
        __syncthreads();
    }
    if (j == 0) out[g] = sred[0] + b2[0];
}

// ---------------- host ----------------
static float* symaddrf(const void* s) { void* p = nullptr; cudaGetSymbolAddress(&p, s); return (float*)p; }
static int*   symaddri(const void* s) { void* p = nullptr; cudaGetSymbolAddress(&p, s); return (int*)p; }

extern "C" void kernel_launch(void* const* d_in, const int* in_sizes, int n_in,
                              void* d_out, int out_size)
{
    const float* nf      = (const float*)d_in[0];
    const int*   ei      = (const int*)  d_in[1];
    const int*   bidx    = (const int*)  d_in[2];
    const float* emb_W   = (const float*)d_in[3];
    const float* emb_b   = (const float*)d_in[4];
    const float* emb_g   = (const float*)d_in[5];
    const float* emb_beta= (const float*)d_in[6];
    const float* msg_W   = (const float*)d_in[7];
    const float* msg_b   = (const float*)d_in[8];
    const float* att_W   = (const float*)d_in[9];
    const float* att_b   = (const float*)d_in[10];
    const float* gru_Wih = (const float*)d_in[11];
    const float* gru_bih = (const float*)d_in[12];
    const float* gru_Whh = (const float*)d_in[13];
    const float* gru_bhh = (const float*)d_in[14];
    const float* bn_g    = (const float*)d_in[15];
    const float* bn_b    = (const float*)d_in[16];
    const float* ro_W1   = (const float*)d_in[17];
    const float* ro_b1   = (const float*)d_in[18];
    const float* ro_W2   = (const float*)d_in[19];
    const float* ro_b2   = (const float*)d_in[20];
    float* out = (float*)d_out;

    float* x    = symaddrf(g_x);
    float* h    = symaddrf(g_h);
    float* m    = symaddrf(g_m);
    float* agg  = symaddrf(g_agg);
    float* gi   = symaddrf(g_gi);
    float* gh   = symaddrf(g_gh);
    float* as_  = symaddrf(g_as);
    float* ad_  = symaddrf(g_ad);
    float* st   = symaddrf(g_stats);
    float* gr   = symaddrf(g_gr);
    float* Wpad = symaddrf(g_Wpad);
    float* Wmh  = symaddrf(g_Wmh);
    float* bmh  = symaddrf(g_bmh);
    uint2* Wf   = (uint2*)symaddrf(g_Wf);
    int* deg  = symaddri(g_deg);
    int* off  = symaddri(g_off);
    int* cur  = symaddri(g_cur);
    int* blk  = symaddri(g_blk);
    int* esrc = symaddri(g_esrc);

    cudaFuncSetAttribute(k_gemm_tc<true>,
                         cudaFuncAttributeMaxDynamicSharedMemorySize, GSMEM_BYTES);
    cudaFuncSetAttribute(k_gemm_tc<false>,
                         cudaFuncAttributeMaxDynamicSharedMemorySize, GSMEM_BYTES);

    const int NH = NND * HH;
    const int GB = (NND + 127) / 128;    // 391 row-blocks
    dim3 gridMB(GB, 1);                  // emb GEMM (D=128)
    dim3 gridMH(GB, 4);                  // fused m+gh GEMM (D=512)
    dim3 gridGI(GB, 3);                  // gi GEMM (D=384)
    dim3 bnB(128, 8);

    // ---- setup + embedding GEMM at launch index 5 (for ncu visibility) ----
    k_prep<<<(NH + 255) / 256, 256>>>(nf, emb_W, msg_W, msg_b, gru_Whh, gru_bhh,
                                      m, Wpad, Wmh, bmh);               // 0
    k_wfrag<<<NWTILES, 256>>>(Wpad, Wmh, gru_Wih, Wf);                  // 1
    k_zinit<<<(NND + 255) / 256, 256>>>(deg, gr);                       // 2
    k_hist<<<(NE + 255) / 256, 256>>>(ei, deg);                         // 3
    k_scan1<<<NB1, 256>>>(deg, off, blk);                               // 4
    k_gemm_tc<true><<<gridMB, 256, GSMEM_BYTES>>>(m, Wf, emb_b, h, h,
                                                  NND, 128, 128, 128, st); // 5 <- ncu
    k_scan2<<<1, 256>>>(blk);                                           // 6
    k_scan3<<<NB1, 256>>>(off, blk, cur);                               // 7
    k_fill<<<(NE + 255) / 256, 256>>>(ei, cur, esrc);                   // 8
    k_bnstats<<<256, bnB>>>(h, st);                                     // 9
    k_bn_fuse<<<(NND * 32 + 255) / 256, 256>>>(h, st, emb_g, emb_beta, att_W,
                                               x, as_, ad_, bidx, gr, 0);

    // ---- 4 message-passing layers ----
    for (int l = 0; l < NL; l++) {
        // fused [m | gh] = x @ [msgW ; Whh]^T  (cols <128 -> m, >=128 -> gh)
        k_gemm_tc<false><<<gridMH, 256, GSMEM_BYTES>>>(
            x, Wf + (size_t)(2 + l * 8) * 2048, bmh + (size_t)l * 512,
            m, gh, NND, 128, 128, 384, nullptr);
        k_gather<<<(NND * 32 + 255) / 256, 256>>>(off, esrc, as_, ad_,
                                                  att_b + l, m, agg);
        // gi = agg @ Wih^T (zeroes stats for k_gru_bn)
        k_gemm_tc<false><<<gridGI, 256, GSMEM_BYTES>>>(
            agg, Wf + (size_t)(2 + NL * 8 + l * 6) * 2048, gru_bih + (size_t)l * 3 * HH,
            gi, gi, NND, 384, 384, 384, st);
        k_gru_bn<<<256, 256>>>(gi, gh, x, h, st);
        if (l < NL - 1) {
            k_bn_fuse<<<(NND * 32 + 255) / 256, 256>>>(
                h, st, bn_g + (size_t)l * HH, bn_b + (size_t)l * HH,
                att_W + (size_t)(l + 1) * 2 * HH, x, as_, ad_, bidx, gr, 0);
        } else {
            k_bn_fuse<<<(NND * 32 + 255) / 256, 256>>>(
                h, st, bn_g + (size_t)l * HH, bn_b + (size_t)l * HH,
                att_W, x, as_, ad_, bidx, gr, 1);
        }
    }

    // ---- readout ----
    k_readout<<<NG, 64>>>(gr, ro_W1, ro_b1, ro_W2, ro_b2, out);

    (void)in_sizes; (void)n_in; (void)out_size;
}